// round 9
// baseline (speedup 1.0000x reference)
#include <cuda_runtime.h>

#define B_   32
#define C_   128
#define H_   36
#define W_   100
#define K_   9
#define PAD_ 4

#define VLP  120   // padded W row in smem (4 + 100 + pad to 120)
#define HLP  48    // padded H col in smem (4 + 36 + 8)
#define HW_  (H_ * W_)

#define WS_FLOATS  (C_ * K_ * 32)   // 36864
#define PR_FLOATS  (C_ * VLP)       // 15360
#define RED_FLOATS 3360

typedef unsigned long long ull;

// Transposed weights: [pass][ci*9*128 + k*128 + co]
__device__ float g_wtT[4][C_ * K_ * C_];
// Scratch: feature map transposed to [B][C][W][H] for horizontal passes
__device__ float g_bufT[B_ * C_ * W_ * H_];

__device__ __forceinline__ ull pk2(float x) {
    ull r;
    asm("mov.b64 %0, {%1, %1};" : "=l"(r) : "f"(x));
    return r;
}
__device__ __forceinline__ void fma2(ull& d, ull a, ull b) {
    asm("fma.rn.f32x2 %0, %1, %2, %0;" : "+l"(d) : "l"(a), "l"(b));
}
__device__ __forceinline__ float2 unpk(ull v) {
    float2 f;
    asm("mov.b64 {%0, %1}, %2;" : "=f"(f.x), "=f"(f.y) : "l"(v));
    return f;
}
// Release/acquire cluster barrier; all cross-CTA data moves via __stcg/__ldcg.
__device__ __forceinline__ void csync() {
    asm volatile("barrier.cluster.arrive.aligned;" ::: "memory");
    asm volatile("barrier.cluster.wait.aligned;" ::: "memory");
}

__global__ void transpose_weights(const float* __restrict__ w0,
                                  const float* __restrict__ w1,
                                  const float* __restrict__ w2,
                                  const float* __restrict__ w3) {
    const int per = C_ * C_ * K_;
    const int total = 4 * per;
    for (int idx = blockIdx.x * blockDim.x + threadIdx.x; idx < total;
         idx += gridDim.x * blockDim.x) {
        int p = idx / per;
        int r = idx - p * per;
        int ci = r / (K_ * C_);
        int k  = (r / C_) % K_;
        int co = r % C_;
        const float* src = (p == 0) ? w0 : (p == 1) ? w1 : (p == 2) ? w2 : w3;
        g_wtT[p][r] = src[(co * C_ + ci) * K_ + k];
    }
}

// ---------------------------------------------------------------------------
// Persistent kernel. Cluster of 4 CTAs = one batch (each CTA owns 32 co).
// Grid (4, 32): blockIdx.x = co-block, blockIdx.y = batch.
// Thread map (full participation): warp = spatial group, lane = 16 co-pairs
// x 2 ci-halves. Each thread accumulates over 64 input channels; partners
// (tid ^ 1) merge partials through smem and split the epilogue.
// ---------------------------------------------------------------------------
__global__ void __cluster_dims__(4, 1, 1) __launch_bounds__(256, 1)
scnn_persistent(float* __restrict__ buf) {
    extern __shared__ float smem[];
    float* ws  = smem;                         // weights [ci][k][32co]
    float* pr  = smem + WS_FLOATS;             // padded row/col buffer
    float* red = smem + WS_FLOATS + PR_FLOATS; // reduction scratch

    const int b = blockIdx.y;
    const int co_base = blockIdx.x * 32;
    const int tid = threadIdx.x;
    const int sg = tid >> 5;            // warp = spatial group (0..7)
    const int copair = (tid >> 1) & 15; // 0..15
    const int cihalf = tid & 1;         // 0..1
    const int co_l = copair * 2;
    const int ci0 = cihalf * 64;
    const int pairid = tid >> 1;        // 0..127

    float* bT = g_bufT;

    for (int pass = 0; pass < 4; pass++) {
        // ---- stage this pass's weight slice [ci][k][32co] into smem ----
        {
            const float* src = g_wtT[pass];
            for (int i = tid; i < C_ * K_ * 8; i += 256) {
                int cik = i >> 3;
                int g = (i & 7) * 4;
                float4 v = *(const float4*)(src + cik * C_ + co_base + g);
                *(float4*)(ws + cik * 32 + g) = v;
            }
        }

        if (pass == 0) {
            // zero smem pads for vertical layout (persist across steps)
            for (int i = tid; i < C_ * VLP; i += 256) {
                int wp = i % VLP;
                if (wp < PAD_ || wp >= PAD_ + W_) pr[i] = 0.f;
            }
        }

        if (pass == 2) {
            __syncthreads();
            // transpose own channel slice: buf[b][c][h][w] -> bT[b][c][w][h]
            for (int c = 0; c < 32; c++) {
                int ch = co_base + c;
                const float* srcp = buf + (size_t)(b * C_ + ch) * HW_;
                for (int i = tid; i < HW_ / 4; i += 256) {
                    float4 v = __ldcg((const float4*)srcp + i);
                    *(float4*)(pr + i * 4) = v;
                }
                __syncthreads();
                float* dstp = bT + (size_t)(b * C_ + ch) * HW_;
                for (int i = tid; i < HW_; i += 256) {
                    int w = i / H_, h = i - w * H_;
                    __stcg(dstp + i, pr[h * W_ + w]);
                }
                __syncthreads();
            }
            // zero smem pads for horizontal layout
            for (int i = tid; i < C_ * HLP; i += 256) {
                int hp = i % HLP;
                if (hp < PAD_ || hp >= PAD_ + H_) pr[i] = 0.f;
            }
            csync();
        }
        __syncthreads();  // weights (and pads) staged

        if (pass < 2) {
            // ================= vertical pass =================
            // 8 warps x 13 w each (104 >= 100); ci split in halves.
            const bool rev = (pass == 1);
            const int wbase = sg * 13;
            for (int s = 1; s < H_; s++) {
                const int cur = rev ? (H_ - 1 - s) : s;
                const int prev = rev ? (cur + 1) : (cur - 1);
                const float* rowg = buf + (size_t)b * C_ * HW_ + prev * W_;
                for (int i = tid; i < C_ * 25; i += 256) {
                    int ci = i / 25, q = i - ci * 25;
                    float4 v = __ldcg((const float4*)(rowg + ci * HW_) + q);
                    *(float4*)(pr + ci * VLP + PAD_ + q * 4) = v;
                }
                __syncthreads();

                ull acc[13];
#pragma unroll
                for (int w = 0; w < 13; w++) acc[w] = 0ull;
                for (int ci = 0; ci < 64; ci++) {
                    const int cig = ci0 + ci;
                    const float* wr = ws + cig * (K_ * 32) + co_l;
                    ull wk[K_];
#pragma unroll
                    for (int k = 0; k < K_; k++)
                        wk[k] = *(const ull*)(wr + k * 32);
                    const float* prow = pr + cig * VLP + wbase;
#pragma unroll
                    for (int j = 0; j < 21; j++) {
                        ull pj = pk2(prow[j]);
                        const int k0 = (j - 12 > 0) ? (j - 12) : 0;
                        const int k1 = (j < 8) ? j : 8;
#pragma unroll
                        for (int k = k0; k <= k1; k++)
                            fma2(acc[j - k], wk[k], pj);
                    }
                }
                __syncthreads();  // done reading pr
                // partner exchange: cihalf1 stores w[0..6], cihalf0 stores w[7..12]
                if (cihalf) {
                    float* dst = red + pairid * 14;
#pragma unroll
                    for (int j = 0; j < 7; j++)
                        *(ull*)(dst + 2 * j) = acc[j];
                } else {
                    float* dst = red + 1792 + pairid * 12;
#pragma unroll
                    for (int j = 0; j < 6; j++)
                        *(ull*)(dst + 2 * j) = acc[7 + j];
                }
                __syncthreads();
                float* o0 = buf + ((size_t)(b * C_ + co_base + co_l) * H_ + cur) * W_ + wbase;
                float* o1 = o0 + HW_;
                if (!cihalf) {
                    const float* srcp = red + pairid * 14;
#pragma unroll
                    for (int j = 0; j < 7; j++) {   // wbase+6 <= 97 < 100 always
                        float2 p = unpk(*(const ull*)(srcp + 2 * j));
                        float2 a = unpk(acc[j]);
                        __stcg(o0 + j, __ldcg(o0 + j) + fmaxf(a.x + p.x, 0.f));
                        __stcg(o1 + j, __ldcg(o1 + j) + fmaxf(a.y + p.y, 0.f));
                    }
                } else {
                    const float* srcp = red + 1792 + pairid * 12;
#pragma unroll
                    for (int j = 0; j < 6; j++) {
                        int wg = wbase + 7 + j;
                        if (wg < W_) {
                            float2 p = unpk(*(const ull*)(srcp + 2 * j));
                            float2 a = unpk(acc[7 + j]);
                            __stcg(o0 + 7 + j, __ldcg(o0 + 7 + j) + fmaxf(a.x + p.x, 0.f));
                            __stcg(o1 + 7 + j, __ldcg(o1 + 7 + j) + fmaxf(a.y + p.y, 0.f));
                        }
                    }
                }
                csync();
            }
        } else {
            // ================= horizontal pass (on bT, [b][c][w][h]) =========
            // 8 warps x 5 h each (40 >= 36); ci split in halves.
            const bool rev = (pass == 3);
            const int hbase = sg * 5;
            for (int s = 1; s < W_; s++) {
                const int cur = rev ? (W_ - 1 - s) : s;
                const int prev = rev ? (cur + 1) : (cur - 1);
                const float* colg = bT + (size_t)b * C_ * HW_ + prev * H_;
                for (int i = tid; i < C_ * 9; i += 256) {
                    int ci = i / 9, q = i - ci * 9;
                    float4 v = __ldcg((const float4*)(colg + ci * HW_) + q);
                    *(float4*)(pr + ci * HLP + PAD_ + q * 4) = v;
                }
                __syncthreads();

                ull acc[5];
#pragma unroll
                for (int h = 0; h < 5; h++) acc[h] = 0ull;
                for (int ci = 0; ci < 64; ci++) {
                    const int cig = ci0 + ci;
                    const float* wr = ws + cig * (K_ * 32) + co_l;
                    ull wk[K_];
#pragma unroll
                    for (int k = 0; k < K_; k++)
                        wk[k] = *(const ull*)(wr + k * 32);
                    const float* prow = pr + cig * HLP + hbase;
#pragma unroll
                    for (int j = 0; j < 13; j++) {
                        ull pj = pk2(prow[j]);
                        const int k0 = (j - 4 > 0) ? (j - 4) : 0;
                        const int k1 = (j < 8) ? j : 8;
#pragma unroll
                        for (int k = k0; k <= k1; k++)
                            fma2(acc[j - k], wk[k], pj);
                    }
                }
                __syncthreads();  // done reading pr
                // partner exchange: cihalf1 stores h[0..2], cihalf0 stores h[3..4]
                if (cihalf) {
                    float* dst = red + pairid * 6;
#pragma unroll
                    for (int j = 0; j < 3; j++)
                        *(ull*)(dst + 2 * j) = acc[j];
                } else {
                    float* dst = red + 768 + pairid * 4;
#pragma unroll
                    for (int j = 0; j < 2; j++)
                        *(ull*)(dst + 2 * j) = acc[3 + j];
                }
                __syncthreads();
                float* o0 = bT + ((size_t)(b * C_ + co_base + co_l) * W_ + cur) * H_ + hbase;
                float* o1 = o0 + HW_;
                if (!cihalf) {
                    const float* srcp = red + pairid * 6;
#pragma unroll
                    for (int j = 0; j < 3; j++) {
                        int hg = hbase + j;
                        if (hg < H_) {
                            float2 p = unpk(*(const ull*)(srcp + 2 * j));
                            float2 a = unpk(acc[j]);
                            __stcg(o0 + j, __ldcg(o0 + j) + fmaxf(a.x + p.x, 0.f));
                            __stcg(o1 + j, __ldcg(o1 + j) + fmaxf(a.y + p.y, 0.f));
                        }
                    }
                } else {
                    const float* srcp = red + 768 + pairid * 4;
#pragma unroll
                    for (int j = 0; j < 2; j++) {
                        int hg = hbase + 3 + j;
                        if (hg < H_) {
                            float2 p = unpk(*(const ull*)(srcp + 2 * j));
                            float2 a = unpk(acc[3 + j]);
                            __stcg(o0 + 3 + j, __ldcg(o0 + 3 + j) + fmaxf(a.x + p.x, 0.f));
                            __stcg(o1 + 3 + j, __ldcg(o1 + 3 + j) + fmaxf(a.y + p.y, 0.f));
                        }
                    }
                }
                csync();
            }
        }
        csync();  // end of pass

        if (pass == 3) {
            // transpose back: bT[b][c][w][h] -> buf[b][c][h][w]
            for (int c = 0; c < 32; c++) {
                int ch = co_base + c;
                const float* srcp = bT + (size_t)(b * C_ + ch) * HW_;
                for (int i = tid; i < HW_ / 4; i += 256) {
                    float4 v = __ldcg((const float4*)srcp + i);
                    *(float4*)(pr + i * 4) = v;
                }
                __syncthreads();
                float* dstp = buf + (size_t)(b * C_ + ch) * HW_;
                for (int i = tid; i < HW_; i += 256) {
                    int h = i / W_, w = i - h * W_;
                    __stcg(dstp + i, pr[w * H_ + h]);
                }
                __syncthreads();
            }
        }
    }
}

extern "C" void kernel_launch(void* const* d_in, const int* in_sizes, int n_in,
                              void* d_out, int out_size) {
    const float* x    = (const float*)d_in[0];
    const float* w_ud = (const float*)d_in[1];
    const float* w_du = (const float*)d_in[2];
    const float* w_lr = (const float*)d_in[3];
    const float* w_rl = (const float*)d_in[4];
    float* buf = (float*)d_out;

    size_t bytes = (size_t)B_ * C_ * HW_ * sizeof(float);
    cudaMemcpyAsync(buf, x, bytes, cudaMemcpyDeviceToDevice, 0);

    transpose_weights<<<288, 256>>>(w_ud, w_du, w_lr, w_rl);

    const int smem_bytes = (WS_FLOATS + PR_FLOATS + RED_FLOATS) * sizeof(float);
    cudaFuncSetAttribute(scnn_persistent,
                         cudaFuncAttributeMaxDynamicSharedMemorySize, smem_bytes);

    dim3 grid(4, B_);
    scnn_persistent<<<grid, 256, smem_bytes>>>(buf);
}

// round 10
// speedup vs baseline: 1.4154x; 1.4154x over previous
#include <cuda_runtime.h>

#define B_   32
#define C_   128
#define H_   36
#define W_   100
#define K_   9
#define PAD_ 4

#define VLP  120   // padded W row in smem (4 + 100 + pad to 120)
#define HLP  48    // padded H col in smem (4 + 36 + 8)
#define HW_  (H_ * W_)

#define WS_FLOATS  (C_ * K_ * 32)   // 36864
#define PR_FLOATS  (C_ * VLP)       // 15360

typedef unsigned long long ull;

// Transposed weights: [pass][ci*9*128 + k*128 + co]
__device__ float g_wtT[4][C_ * K_ * C_];
// Scratch: feature map transposed to [B][C][W][H] for horizontal passes
__device__ float g_bufT[B_ * C_ * W_ * H_];

__device__ __forceinline__ ull pk2(float x) {
    ull r;
    asm("mov.b64 %0, {%1, %1};" : "=l"(r) : "f"(x));
    return r;
}
__device__ __forceinline__ void fma2(ull& d, ull a, ull b) {
    asm("fma.rn.f32x2 %0, %1, %2, %0;" : "+l"(d) : "l"(a), "l"(b));
}
__device__ __forceinline__ float2 unpk(ull v) {
    float2 f;
    asm("mov.b64 {%0, %1}, %2;" : "=f"(f.x), "=f"(f.y) : "l"(v));
    return f;
}
// Release/acquire cluster barrier; all cross-CTA data moves via __stcg/__ldcg.
__device__ __forceinline__ void csync() {
    asm volatile("barrier.cluster.arrive.aligned;" ::: "memory");
    asm volatile("barrier.cluster.wait.aligned;" ::: "memory");
}

__global__ void transpose_weights(const float* __restrict__ w0,
                                  const float* __restrict__ w1,
                                  const float* __restrict__ w2,
                                  const float* __restrict__ w3) {
    const int per = C_ * C_ * K_;
    const int total = 4 * per;
    for (int idx = blockIdx.x * blockDim.x + threadIdx.x; idx < total;
         idx += gridDim.x * blockDim.x) {
        int p = idx / per;
        int r = idx - p * per;
        int ci = r / (K_ * C_);
        int k  = (r / C_) % K_;
        int co = r % C_;
        const float* src = (p == 0) ? w0 : (p == 1) ? w1 : (p == 2) ? w2 : w3;
        g_wtT[p][r] = src[(co * C_ + ci) * K_ + k];
    }
}

// ---------------------------------------------------------------------------
// Persistent kernel. Cluster of 4 CTAs = one batch (each CTA owns 32 co).
// Grid (4, 32). Warp-based balanced tiles: all 8 warps active.
// lane = copair (16) x sub (2 halves of the warp's spatial tile).
// ---------------------------------------------------------------------------
__global__ void __cluster_dims__(4, 1, 1) __launch_bounds__(256, 1)
scnn_persistent(float* __restrict__ buf) {
    extern __shared__ float smem[];
    float* ws = smem;              // weights [ci][k][32co]
    float* pr = smem + WS_FLOATS;  // padded row/col buffer

    const int b = blockIdx.y;
    const int co_base = blockIdx.x * 32;
    const int tid = threadIdx.x;
    const int wid = tid >> 5;           // warp 0..7
    const int copair = tid & 15;        // 0..15
    const int sub = (tid >> 4) & 1;     // half-warp sub-tile
    const int co_l = copair * 2;

    float* bT = g_bufT;

    for (int pass = 0; pass < 4; pass++) {
        // ---- stage this pass's weight slice [ci][k][32co] into smem ----
        {
            const float* src = g_wtT[pass];
            for (int i = tid; i < C_ * K_ * 8; i += 256) {
                int cik = i >> 3;
                int g = (i & 7) * 4;
                float4 v = *(const float4*)(src + cik * C_ + co_base + g);
                *(float4*)(ws + cik * 32 + g) = v;
            }
        }

        if (pass == 0) {
            for (int i = tid; i < C_ * VLP; i += 256) {
                int wp = i % VLP;
                if (wp < PAD_ || wp >= PAD_ + W_) pr[i] = 0.f;
            }
        }

        if (pass == 2) {
            __syncthreads();
            // transpose own channel slice: buf[b][c][h][w] -> bT[b][c][w][h]
            for (int c = 0; c < 32; c++) {
                int ch = co_base + c;
                const float* srcp = buf + (size_t)(b * C_ + ch) * HW_;
                for (int i = tid; i < HW_ / 4; i += 256) {
                    float4 v = __ldcg((const float4*)srcp + i);
                    *(float4*)(pr + i * 4) = v;
                }
                __syncthreads();
                float* dstp = bT + (size_t)(b * C_ + ch) * HW_;
                for (int i = tid; i < HW_; i += 256) {
                    int w = i / H_, h = i - w * H_;
                    __stcg(dstp + i, pr[h * W_ + w]);
                }
                __syncthreads();
            }
            // zero smem pads for horizontal layout
            for (int i = tid; i < C_ * HLP; i += 256) {
                int hp = i % HLP;
                if (hp < PAD_ || hp >= PAD_ + H_) pr[i] = 0.f;
            }
            csync();
        }
        __syncthreads();  // weights (and pads) staged

        if (pass < 2) {
            // ================= vertical pass =================
            // warps 0-3: 13-w tiles (sub 7+6, acc[7]); warps 4-7: 12-w (6+6, acc[6]).
            const bool rev = (pass == 1);
            int base, nuse;
            if (wid < 4) { base = wid * 13 + sub * 7; nuse = 7 - sub; }
            else         { base = 52 + (wid - 4) * 12 + sub * 6; nuse = 6; }

            for (int s = 1; s < H_; s++) {
                const int cur = rev ? (H_ - 1 - s) : s;
                const int prev = rev ? (cur + 1) : (cur - 1);
                const float* rowg = buf + (size_t)b * C_ * HW_ + prev * W_;
                for (int i = tid; i < C_ * 25; i += 256) {
                    int ci = i / 25, q = i - ci * 25;
                    float4 v = __ldcg((const float4*)(rowg + ci * HW_) + q);
                    *(float4*)(pr + ci * VLP + PAD_ + q * 4) = v;
                }
                __syncthreads();

                if (wid < 4) {
                    ull acc[7];
#pragma unroll
                    for (int j = 0; j < 7; j++) acc[j] = 0ull;
                    for (int ci = 0; ci < C_; ci++) {
                        const float* prow = pr + ci * VLP + base;
                        ull pv[15];
#pragma unroll
                        for (int j = 0; j < 15; j++) pv[j] = pk2(prow[j]);
                        const float* wr = ws + ci * (K_ * 32) + co_l;
#pragma unroll
                        for (int k = 0; k < K_; k++) {
                            ull wv = *(const ull*)(wr + k * 32);
#pragma unroll
                            for (int j = 0; j < 7; j++)
                                fma2(acc[j], wv, pv[k + j]);
                        }
                    }
                    float* o0 = buf + ((size_t)(b * C_ + co_base + co_l) * H_ + cur) * W_ + base;
                    float* o1 = o0 + HW_;
#pragma unroll
                    for (int j = 0; j < 7; j++) {
                        if (j < nuse) {
                            float2 v = unpk(acc[j]);
                            __stcg(o0 + j, __ldcg(o0 + j) + fmaxf(v.x, 0.f));
                            __stcg(o1 + j, __ldcg(o1 + j) + fmaxf(v.y, 0.f));
                        }
                    }
                } else {
                    ull acc[6];
#pragma unroll
                    for (int j = 0; j < 6; j++) acc[j] = 0ull;
                    for (int ci = 0; ci < C_; ci++) {
                        const float* prow = pr + ci * VLP + base;
                        ull pv[14];
#pragma unroll
                        for (int j = 0; j < 14; j++) pv[j] = pk2(prow[j]);
                        const float* wr = ws + ci * (K_ * 32) + co_l;
#pragma unroll
                        for (int k = 0; k < K_; k++) {
                            ull wv = *(const ull*)(wr + k * 32);
#pragma unroll
                            for (int j = 0; j < 6; j++)
                                fma2(acc[j], wv, pv[k + j]);
                        }
                    }
                    float* o0 = buf + ((size_t)(b * C_ + co_base + co_l) * H_ + cur) * W_ + base;
                    float* o1 = o0 + HW_;
#pragma unroll
                    for (int j = 0; j < 6; j++) {
                        float2 v = unpk(acc[j]);
                        __stcg(o0 + j, __ldcg(o0 + j) + fmaxf(v.x, 0.f));
                        __stcg(o1 + j, __ldcg(o1 + j) + fmaxf(v.y, 0.f));
                    }
                }
                csync();
            }
        } else {
            // ================= horizontal pass (on bT, [b][c][w][h]) =========
            // warps 0-3: 5-h tiles (sub 3+2, acc[3]); warps 4-7: 4-h (2+2, acc[2]).
            const bool rev = (pass == 3);
            int base, nuse;
            if (wid < 4) { base = wid * 5 + sub * 3; nuse = 3 - sub; }
            else         { base = 20 + (wid - 4) * 4 + sub * 2; nuse = 2; }

            for (int s = 1; s < W_; s++) {
                const int cur = rev ? (W_ - 1 - s) : s;
                const int prev = rev ? (cur + 1) : (cur - 1);
                const float* colg = bT + (size_t)b * C_ * HW_ + prev * H_;
                for (int i = tid; i < C_ * 9; i += 256) {
                    int ci = i / 9, q = i - ci * 9;
                    float4 v = __ldcg((const float4*)(colg + ci * HW_) + q);
                    *(float4*)(pr + ci * HLP + PAD_ + q * 4) = v;
                }
                __syncthreads();

                if (wid < 4) {
                    ull acc[3];
                    acc[0] = acc[1] = acc[2] = 0ull;
                    for (int ci = 0; ci < C_; ci++) {
                        const float* prow = pr + ci * HLP + base;
                        ull pv[11];
#pragma unroll
                        for (int j = 0; j < 11; j++) pv[j] = pk2(prow[j]);
                        const float* wr = ws + ci * (K_ * 32) + co_l;
#pragma unroll
                        for (int k = 0; k < K_; k++) {
                            ull wv = *(const ull*)(wr + k * 32);
#pragma unroll
                            for (int j = 0; j < 3; j++)
                                fma2(acc[j], wv, pv[k + j]);
                        }
                    }
                    float* o0 = bT + ((size_t)(b * C_ + co_base + co_l) * W_ + cur) * H_ + base;
                    float* o1 = o0 + HW_;
#pragma unroll
                    for (int j = 0; j < 3; j++) {
                        if (j < nuse) {
                            float2 v = unpk(acc[j]);
                            __stcg(o0 + j, __ldcg(o0 + j) + fmaxf(v.x, 0.f));
                            __stcg(o1 + j, __ldcg(o1 + j) + fmaxf(v.y, 0.f));
                        }
                    }
                } else {
                    ull acc[2];
                    acc[0] = acc[1] = 0ull;
                    for (int ci = 0; ci < C_; ci++) {
                        const float* prow = pr + ci * HLP + base;
                        ull pv[10];
#pragma unroll
                        for (int j = 0; j < 10; j++) pv[j] = pk2(prow[j]);
                        const float* wr = ws + ci * (K_ * 32) + co_l;
#pragma unroll
                        for (int k = 0; k < K_; k++) {
                            ull wv = *(const ull*)(wr + k * 32);
#pragma unroll
                            for (int j = 0; j < 2; j++)
                                fma2(acc[j], wv, pv[k + j]);
                        }
                    }
                    float* o0 = bT + ((size_t)(b * C_ + co_base + co_l) * W_ + cur) * H_ + base;
                    float* o1 = o0 + HW_;
#pragma unroll
                    for (int j = 0; j < 2; j++) {
                        float2 v = unpk(acc[j]);
                        __stcg(o0 + j, __ldcg(o0 + j) + fmaxf(v.x, 0.f));
                        __stcg(o1 + j, __ldcg(o1 + j) + fmaxf(v.y, 0.f));
                    }
                }
                csync();
            }
        }
        csync();  // end of pass

        if (pass == 3) {
            // transpose back: bT[b][c][w][h] -> buf[b][c][h][w]
            for (int c = 0; c < 32; c++) {
                int ch = co_base + c;
                const float* srcp = bT + (size_t)(b * C_ + ch) * HW_;
                for (int i = tid; i < HW_ / 4; i += 256) {
                    float4 v = __ldcg((const float4*)srcp + i);
                    *(float4*)(pr + i * 4) = v;
                }
                __syncthreads();
                float* dstp = buf + (size_t)(b * C_ + ch) * HW_;
                for (int i = tid; i < HW_; i += 256) {
                    int h = i / W_, w = i - h * W_;
                    __stcg(dstp + i, pr[w * H_ + h]);
                }
                __syncthreads();
            }
        }
    }
}

extern "C" void kernel_launch(void* const* d_in, const int* in_sizes, int n_in,
                              void* d_out, int out_size) {
    const float* x    = (const float*)d_in[0];
    const float* w_ud = (const float*)d_in[1];
    const float* w_du = (const float*)d_in[2];
    const float* w_lr = (const float*)d_in[3];
    const float* w_rl = (const float*)d_in[4];
    float* buf = (float*)d_out;

    size_t bytes = (size_t)B_ * C_ * HW_ * sizeof(float);
    cudaMemcpyAsync(buf, x, bytes, cudaMemcpyDeviceToDevice, 0);

    transpose_weights<<<288, 256>>>(w_ud, w_du, w_lr, w_rl);

    const int smem_bytes = (WS_FLOATS + PR_FLOATS) * sizeof(float);  // 208896
    cudaFuncSetAttribute(scnn_persistent,
                         cudaFuncAttributeMaxDynamicSharedMemorySize, smem_bytes);

    dim3 grid(4, B_);
    scnn_persistent<<<grid, 256, smem_bytes>>>(buf);
}

// round 11
// speedup vs baseline: 1.9658x; 1.3888x over previous
#include <cuda_runtime.h>

#define B_   32
#define C_   128
#define H_   36
#define W_   100
#define K_   9
#define PAD_ 4

#define VLP  120   // padded W row in smem (4 + 100 + pad to 120)
#define HLP  48    // padded H col in smem (4 + 36 + 8)
#define HW_  (H_ * W_)

#define NT   512   // threads per CTA (16 warps)

#define WS_FLOATS  (C_ * K_ * 32)   // 36864
#define PR_FLOATS  (C_ * VLP)       // 15360

typedef unsigned long long ull;

// Transposed weights: [pass][ci*9*128 + k*128 + co]
__device__ float g_wtT[4][C_ * K_ * C_];
// Scratch: feature map transposed to [B][C][W][H] for horizontal passes
__device__ float g_bufT[B_ * C_ * W_ * H_];

__device__ __forceinline__ ull pk2(float x) {
    ull r;
    asm("mov.b64 %0, {%1, %1};" : "=l"(r) : "f"(x));
    return r;
}
__device__ __forceinline__ void fma2(ull& d, ull a, ull b) {
    asm("fma.rn.f32x2 %0, %1, %2, %0;" : "+l"(d) : "l"(a), "l"(b));
}
__device__ __forceinline__ float2 unpk(ull v) {
    float2 f;
    asm("mov.b64 {%0, %1}, %2;" : "=f"(f.x), "=f"(f.y) : "l"(v));
    return f;
}
// Release/acquire cluster barrier; all cross-CTA data moves via __stcg/__ldcg.
__device__ __forceinline__ void csync() {
    asm volatile("barrier.cluster.arrive.aligned;" ::: "memory");
    asm volatile("barrier.cluster.wait.aligned;" ::: "memory");
}

__global__ void transpose_weights(const float* __restrict__ w0,
                                  const float* __restrict__ w1,
                                  const float* __restrict__ w2,
                                  const float* __restrict__ w3) {
    const int per = C_ * C_ * K_;
    const int total = 4 * per;
    for (int idx = blockIdx.x * blockDim.x + threadIdx.x; idx < total;
         idx += gridDim.x * blockDim.x) {
        int p = idx / per;
        int r = idx - p * per;
        int ci = r / (K_ * C_);
        int k  = (r / C_) % K_;
        int co = r % C_;
        const float* src = (p == 0) ? w0 : (p == 1) ? w1 : (p == 2) ? w2 : w3;
        g_wtT[p][r] = src[(co * C_ + ci) * K_ + k];
    }
}

// ---------------------------------------------------------------------------
// Persistent kernel. Cluster of 4 CTAs = one batch (each CTA owns 32 co).
// Grid (4, 32), 512 threads (16 warps). sgrp = tid>>4 (32 groups of 16
// copair lanes). Vertical: 25 groups x 4 w (exact, aligned). Horizontal:
// 18 groups x 2 h (exact, aligned).
// ---------------------------------------------------------------------------
__global__ void __cluster_dims__(4, 1, 1) __launch_bounds__(NT, 1)
scnn_persistent(float* __restrict__ buf) {
    extern __shared__ float smem[];
    float* ws = smem;              // weights [ci][k][32co]
    float* pr = smem + WS_FLOATS;  // padded row/col buffer

    const int b = blockIdx.y;
    const int co_base = blockIdx.x * 32;
    const int tid = threadIdx.x;
    const int copair = tid & 15;   // 0..15
    const int sgrp = tid >> 4;     // 0..31 spatial group
    const int co_l = copair * 2;

    float* bT = g_bufT;

    for (int pass = 0; pass < 4; pass++) {
        // ---- stage this pass's weight slice [ci][k][32co] into smem ----
        {
            const float* src = g_wtT[pass];
            for (int i = tid; i < C_ * K_ * 8; i += NT) {
                int cik = i >> 3;
                int g = (i & 7) * 4;
                float4 v = *(const float4*)(src + cik * C_ + co_base + g);
                *(float4*)(ws + cik * 32 + g) = v;
            }
        }

        if (pass == 0) {
            for (int i = tid; i < C_ * VLP; i += NT) {
                int wp = i % VLP;
                if (wp < PAD_ || wp >= PAD_ + W_) pr[i] = 0.f;
            }
        }

        if (pass == 2) {
            __syncthreads();
            // transpose own channel slice: buf[b][c][h][w] -> bT[b][c][w][h]
            for (int c = 0; c < 32; c++) {
                int ch = co_base + c;
                const float* srcp = buf + (size_t)(b * C_ + ch) * HW_;
                for (int i = tid; i < HW_ / 4; i += NT) {
                    float4 v = __ldcg((const float4*)srcp + i);
                    *(float4*)(pr + i * 4) = v;
                }
                __syncthreads();
                float* dstp = bT + (size_t)(b * C_ + ch) * HW_;
                for (int i = tid; i < HW_; i += NT) {
                    int w = i / H_, h = i - w * H_;
                    __stcg(dstp + i, pr[h * W_ + w]);
                }
                __syncthreads();
            }
            // zero smem pads for horizontal layout
            for (int i = tid; i < C_ * HLP; i += NT) {
                int hp = i % HLP;
                if (hp < PAD_ || hp >= PAD_ + H_) pr[i] = 0.f;
            }
            csync();
        }
        __syncthreads();  // weights (and pads) staged

        if (pass < 2) {
            // ================= vertical pass =================
            // 25 groups x 4 w = 100 exact; base = sgrp*4 (float4-aligned).
            const bool rev = (pass == 1);
            const int wbase = sgrp * 4;
            for (int s = 1; s < H_; s++) {
                const int cur = rev ? (H_ - 1 - s) : s;
                const int prev = rev ? (cur + 1) : (cur - 1);
                const float* rowg = buf + (size_t)b * C_ * HW_ + prev * W_;
                for (int i = tid; i < C_ * 25; i += NT) {
                    int ci = i / 25, q = i - ci * 25;
                    float4 v = __ldcg((const float4*)(rowg + ci * HW_) + q);
                    *(float4*)(pr + ci * VLP + PAD_ + q * 4) = v;
                }
                __syncthreads();

                if (sgrp < 25) {
                    ull acc[4];
                    acc[0] = acc[1] = acc[2] = acc[3] = 0ull;
                    for (int ci = 0; ci < C_; ci++) {
                        // padded origin: out pixel (wbase+j) reads padded
                        // inputs (wbase+j) .. (wbase+j+8)
                        const float* prp = pr + ci * VLP + wbase;
                        float4 q0 = *(const float4*)(prp);
                        float4 q1 = *(const float4*)(prp + 4);
                        float4 q2 = *(const float4*)(prp + 8);
                        ull pv[12];
                        pv[0]  = pk2(q0.x); pv[1]  = pk2(q0.y);
                        pv[2]  = pk2(q0.z); pv[3]  = pk2(q0.w);
                        pv[4]  = pk2(q1.x); pv[5]  = pk2(q1.y);
                        pv[6]  = pk2(q1.z); pv[7]  = pk2(q1.w);
                        pv[8]  = pk2(q2.x); pv[9]  = pk2(q2.y);
                        pv[10] = pk2(q2.z); pv[11] = pk2(q2.w);
                        const float* wr = ws + ci * (K_ * 32) + co_l;
#pragma unroll
                        for (int k = 0; k < K_; k++) {
                            ull wv = *(const ull*)(wr + k * 32);
#pragma unroll
                            for (int j = 0; j < 4; j++)
                                fma2(acc[j], wv, pv[k + j]);
                        }
                    }
                    // vectorized += relu epilogue (two channel rows)
                    float a0[4], a1[4];
#pragma unroll
                    for (int j = 0; j < 4; j++) {
                        float2 v = unpk(acc[j]);
                        a0[j] = fmaxf(v.x, 0.f);
                        a1[j] = fmaxf(v.y, 0.f);
                    }
                    float* o0 = buf + ((size_t)(b * C_ + co_base + co_l) * H_ + cur) * W_ + wbase;
                    float* o1 = o0 + HW_;
                    float4 t;
                    t = __ldcg((float4*)o0);
                    t.x += a0[0]; t.y += a0[1]; t.z += a0[2]; t.w += a0[3];
                    __stcg((float4*)o0, t);
                    t = __ldcg((float4*)o1);
                    t.x += a1[0]; t.y += a1[1]; t.z += a1[2]; t.w += a1[3];
                    __stcg((float4*)o1, t);
                }
                csync();
            }
        } else {
            // ================= horizontal pass (on bT, [b][c][w][h]) =========
            // 18 groups x 2 h = 36 exact; base = sgrp*2 (float2-aligned).
            const bool rev = (pass == 3);
            const int hbase = sgrp * 2;
            for (int s = 1; s < W_; s++) {
                const int cur = rev ? (W_ - 1 - s) : s;
                const int prev = rev ? (cur + 1) : (cur - 1);
                const float* colg = bT + (size_t)b * C_ * HW_ + prev * H_;
                for (int i = tid; i < C_ * 9; i += NT) {
                    int ci = i / 9, q = i - ci * 9;
                    float4 v = __ldcg((const float4*)(colg + ci * HW_) + q);
                    *(float4*)(pr + ci * HLP + PAD_ + q * 4) = v;
                }
                __syncthreads();

                if (sgrp < 18) {
                    ull acc[2];
                    acc[0] = acc[1] = 0ull;
                    for (int ci = 0; ci < C_; ci++) {
                        const float* prp = pr + ci * HLP + hbase;
                        float2 d0 = *(const float2*)(prp);
                        float2 d1 = *(const float2*)(prp + 2);
                        float2 d2 = *(const float2*)(prp + 4);
                        float2 d3 = *(const float2*)(prp + 6);
                        float2 d4 = *(const float2*)(prp + 8);
                        ull pv[10];
                        pv[0] = pk2(d0.x); pv[1] = pk2(d0.y);
                        pv[2] = pk2(d1.x); pv[3] = pk2(d1.y);
                        pv[4] = pk2(d2.x); pv[5] = pk2(d2.y);
                        pv[6] = pk2(d3.x); pv[7] = pk2(d3.y);
                        pv[8] = pk2(d4.x); pv[9] = pk2(d4.y);
                        const float* wr = ws + ci * (K_ * 32) + co_l;
#pragma unroll
                        for (int k = 0; k < K_; k++) {
                            ull wv = *(const ull*)(wr + k * 32);
                            fma2(acc[0], wv, pv[k]);
                            fma2(acc[1], wv, pv[k + 1]);
                        }
                    }
                    float2 v0 = unpk(acc[0]);
                    float2 v1 = unpk(acc[1]);
                    float* o0 = bT + ((size_t)(b * C_ + co_base + co_l) * W_ + cur) * H_ + hbase;
                    float* o1 = o0 + HW_;
                    float2 t;
                    t = __ldcg((float2*)o0);
                    t.x += fmaxf(v0.x, 0.f); t.y += fmaxf(v1.x, 0.f);
                    __stcg((float2*)o0, t);
                    t = __ldcg((float2*)o1);
                    t.x += fmaxf(v0.y, 0.f); t.y += fmaxf(v1.y, 0.f);
                    __stcg((float2*)o1, t);
                }
                csync();
            }
        }
        csync();  // end of pass

        if (pass == 3) {
            // transpose back: bT[b][c][w][h] -> buf[b][c][h][w]
            for (int c = 0; c < 32; c++) {
                int ch = co_base + c;
                const float* srcp = bT + (size_t)(b * C_ + ch) * HW_;
                for (int i = tid; i < HW_ / 4; i += NT) {
                    float4 v = __ldcg((const float4*)srcp + i);
                    *(float4*)(pr + i * 4) = v;
                }
                __syncthreads();
                float* dstp = buf + (size_t)(b * C_ + ch) * HW_;
                for (int i = tid; i < HW_; i += NT) {
                    int h = i / W_, w = i - h * W_;
                    __stcg(dstp + i, pr[w * H_ + h]);
                }
                __syncthreads();
            }
        }
    }
}

extern "C" void kernel_launch(void* const* d_in, const int* in_sizes, int n_in,
                              void* d_out, int out_size) {
    const float* x    = (const float*)d_in[0];
    const float* w_ud = (const float*)d_in[1];
    const float* w_du = (const float*)d_in[2];
    const float* w_lr = (const float*)d_in[3];
    const float* w_rl = (const float*)d_in[4];
    float* buf = (float*)d_out;

    size_t bytes = (size_t)B_ * C_ * HW_ * sizeof(float);
    cudaMemcpyAsync(buf, x, bytes, cudaMemcpyDeviceToDevice, 0);

    transpose_weights<<<288, 256>>>(w_ud, w_du, w_lr, w_rl);

    const int smem_bytes = (WS_FLOATS + PR_FLOATS) * sizeof(float);  // 208896
    cudaFuncSetAttribute(scnn_persistent,
                         cudaFuncAttributeMaxDynamicSharedMemorySize, smem_bytes);

    dim3 grid(4, B_);
    scnn_persistent<<<grid, NT, smem_bytes>>>(buf);
}